// round 9
// baseline (speedup 1.0000x reference)
#include <cuda_runtime.h>

#define NN    131072
#define KK    27
#define FINN  3
#define FOUTN 32
#define EPSB  1e-5f

#define THR2    256   // threads per stage2 block
#define TILE2   512   // nodes per stage2 block (2 nodes/thread)
#define RSTRIDE 36    // staging row stride in floats (144B: conflict-free)
#define STGF    (TILE2 * RSTRIDE)   // 18432 floats

// Scratch: h = silu(bn(gemm1)) [N,32] fp32 (16MB)
__device__ __align__(256) float g_h[NN * FOUTN];

typedef unsigned long long ull;

__device__ __forceinline__ ull fma2(ull a, ull b, ull c) {
    ull d;
    asm("fma.rn.f32x2 %0, %1, %2, %3;" : "=l"(d) : "l"(a), "l"(b), "l"(c));
    return d;
}
__device__ __forceinline__ ull pack2(float x) {
    ull r; unsigned u = __float_as_uint(x);
    asm("mov.b64 %0, {%1, %2};" : "=l"(r) : "r"(u), "r"(u));
    return r;
}
__device__ __forceinline__ float2 unpack2(ull v) {
    unsigned lo, hi;
    asm("mov.b64 {%0, %1}, %2;" : "=r"(lo), "=r"(hi) : "l"(v));
    return make_float2(__uint_as_float(lo), __uint_as_float(hi));
}

// ============================================================================
// Stage 1: h[n,:] = silu(bn1( sum_k sum_f x[nbr[n,k],f] * w1[k,f,:] ))
// one thread per node; direct 3-float gather (x table is L2-resident, 1.5MB)
// ============================================================================
__global__ __launch_bounds__(256)
void stage1_kernel(const float* __restrict__ x_feats,
                   const int*   __restrict__ nbr,
                   const float* __restrict__ w1,
                   const float* __restrict__ gamma1,
                   const float* __restrict__ beta1,
                   const float* __restrict__ mean1,
                   const float* __restrict__ var1)
{
    __shared__ __align__(16) float w1s[KK * FINN * FOUTN];
    __shared__ float s_scale[FOUTN], s_shift[FOUTN];

    const int tid = threadIdx.x;
    for (int i = tid; i < (KK * FINN * FOUTN) / 4; i += blockDim.x)
        ((float4*)w1s)[i] = ((const float4*)w1)[i];
    if (tid < FOUTN) {
        float sc = gamma1[tid] * rsqrtf(var1[tid] + EPSB);
        s_scale[tid] = sc;
        s_shift[tid] = beta1[tid] - mean1[tid] * sc;
    }
    __syncthreads();

    const int n = blockIdx.x * blockDim.x + tid;
    const int* nrow = nbr + (size_t)n * KK;

    ull acc[16];
    #pragma unroll
    for (int i = 0; i < 16; i++) acc[i] = 0ULL;

    int idx_next = nrow[0];
    #pragma unroll 1
    for (int k = 0; k < KK; k++) {
        const int idx = idx_next;
        if (k + 1 < KK) idx_next = nrow[k + 1];
        const float* xr = x_feats + (size_t)idx * FINN;
        float xv[3];
        xv[0] = __ldg(xr); xv[1] = __ldg(xr + 1); xv[2] = __ldg(xr + 2);
        #pragma unroll
        for (int f = 0; f < FINN; f++) {
            ull s2 = pack2(xv[f]);
            const ulonglong2* wp = (const ulonglong2*)(w1s + (k * FINN + f) * FOUTN);
            #pragma unroll
            for (int j = 0; j < 8; j++) {
                ulonglong2 w = wp[j];
                acc[2 * j]     = fma2(s2, w.x, acc[2 * j]);
                acc[2 * j + 1] = fma2(s2, w.y, acc[2 * j + 1]);
            }
        }
    }

    float outv[FOUTN];
    #pragma unroll
    for (int i = 0; i < 16; i++) {
        float2 v = unpack2(acc[i]);
        outv[2 * i] = v.x; outv[2 * i + 1] = v.y;
    }
    float4* dst = (float4*)(g_h + (size_t)n * FOUTN);
    #pragma unroll
    for (int j = 0; j < 8; j++) {
        float4 o4; float v;
        v = outv[4*j+0] * s_scale[4*j+0] + s_shift[4*j+0]; o4.x = v / (1.f + __expf(-v));
        v = outv[4*j+1] * s_scale[4*j+1] + s_shift[4*j+1]; o4.y = v / (1.f + __expf(-v));
        v = outv[4*j+2] * s_scale[4*j+2] + s_shift[4*j+2]; o4.z = v / (1.f + __expf(-v));
        v = outv[4*j+3] * s_scale[4*j+3] + s_shift[4*j+3]; o4.w = v / (1.f + __expf(-v));
        dst[j] = o4;
    }
}

// ============================================================================
// Stage 2: x_out[n,:] = sum_k h[nbr[n,k],:] @ w2[k,:,:]; fuse point branch.
// 256 thr x 2 nodes; per-k: cooperative LDG->STS gather (chunked, low regs),
// w2 streamed via 4-reg double buffer into 4KB smem (broadcast LDS reads).
// ~82KB smem -> 2 CTAs/SM; no cp.async, no register prefetch.
// ============================================================================
#define SMEM2_FLOATS (STGF + 1024 + 1024 + 96 + 32)
#define SMEM2_BYTES  (SMEM2_FLOATS * 4)

__global__ __launch_bounds__(THR2, 2)
void stage2_kernel(const float* __restrict__ z_feats,
                   const int*   __restrict__ nbr,
                   const float* __restrict__ w2,
                   const float* __restrict__ mlp_w,
                   const float* __restrict__ mlp_b,
                   const float* __restrict__ mlp_gamma,
                   const float* __restrict__ mlp_beta,
                   const float* __restrict__ mlp_mean,
                   const float* __restrict__ mlp_var,
                   float* __restrict__ out,
                   int N, int copies)
{
    extern __shared__ __align__(16) float sm[];
    float* stg  = sm;                        // 18432 floats (512 rows x 36)
    float* w2s  = sm + STGF;                 // 1024 floats (current k)
    int*   idxb = (int*)(w2s + 1024);        // [2][512] ints
    float* zw   = (float*)(idxb + 1024);     // 96
    float* zb   = zw + 96;                   // 32

    const int t = threadIdx.x;
    const int base  = blockIdx.x * TILE2;
    const int node0 = base + t;
    const int node1 = base + THR2 + t;
    const int* nr0 = nbr + (size_t)node0 * KK;
    const int* nr1 = nbr + (size_t)node1 * KK;

    if (t < FOUTN) {
        float sc = mlp_gamma[t] * rsqrtf(mlp_var[t] + EPSB);
        float sh = mlp_beta[t] - mlp_mean[t] * sc;
        zb[t] = mlp_b[t] * sc + sh;
        #pragma unroll
        for (int f = 0; f < FINN; f++)
            zw[f * FOUTN + t] = mlp_w[f * FOUTN + t] * sc;
    }

    // prologue: idx for k=0; w2[0] into regs
    idxb[t]        = nr0[0];
    idxb[THR2 + t] = nr1[0];
    float4 w2reg = ((const float4*)w2)[t];
    __syncthreads();

    ull acc0[16], acc1[16];
    #pragma unroll
    for (int i = 0; i < 16; i++) { acc0[i] = 0ULL; acc1[i] = 0ULL; }

    #pragma unroll 1
    for (int k = 0; k < KK; k++) {
        // ---- gather phase: 16 segs/thread, chunks of 4 (low reg pressure)
        const int* ib = idxb + (k & 1) * TILE2;
        #pragma unroll
        for (int c4 = 0; c4 < 4; c4++) {
            float4 tmp[4];
            #pragma unroll
            for (int q = 0; q < 4; q++) {
                int s = (c4 * 4 + q) * THR2 + t;
                int r = s >> 3, g = s & 7;
                tmp[q] = ((const float4*)(g_h + (size_t)ib[r] * FOUTN))[g];
            }
            #pragma unroll
            for (int q = 0; q < 4; q++) {
                int s = (c4 * 4 + q) * THR2 + t;
                int r = s >> 3, g = s & 7;
                *(float4*)(stg + r * RSTRIDE + g * 4) = tmp[q];
            }
        }
        ((float4*)w2s)[t] = w2reg;                     // w2 for this k
        if (k + 1 < KK) {                              // prep next k
            w2reg = ((const float4*)(w2 + (k + 1) * 1024))[t];
            int* ob = idxb + ((k + 1) & 1) * TILE2;
            ob[t]        = nr0[k + 1];
            ob[THR2 + t] = nr1[k + 1];
        }
        __syncthreads();    // stage + w2s visible

        // ---- compute phase: both nodes share every (broadcast) w2 LDS
        const float* myrow0 = stg + t * RSTRIDE;
        const float* myrow1 = stg + (THR2 + t) * RSTRIDE;
        #pragma unroll
        for (int c = 0; c < 4; c++) {
            float4 a0 = *(const float4*)(myrow0 + c * 8);
            float4 b0 = *(const float4*)(myrow0 + c * 8 + 4);
            float4 a1 = *(const float4*)(myrow1 + c * 8);
            float4 b1 = *(const float4*)(myrow1 + c * 8 + 4);
            float h0v[8] = {a0.x, a0.y, a0.z, a0.w, b0.x, b0.y, b0.z, b0.w};
            float h1v[8] = {a1.x, a1.y, a1.z, a1.w, b1.x, b1.y, b1.z, b1.w};
            #pragma unroll
            for (int ff = 0; ff < 8; ff++) {
                int f = c * 8 + ff;
                ull s0 = pack2(h0v[ff]);
                ull s1 = pack2(h1v[ff]);
                const ulonglong2* wp = (const ulonglong2*)(w2s + f * FOUTN);
                #pragma unroll
                for (int j = 0; j < 8; j++) {
                    ulonglong2 w = wp[j];
                    acc0[2*j]   = fma2(s0, w.x, acc0[2*j]);
                    acc0[2*j+1] = fma2(s0, w.y, acc0[2*j+1]);
                    acc1[2*j]   = fma2(s1, w.x, acc1[2*j]);
                    acc1[2*j+1] = fma2(s1, w.y, acc1[2*j+1]);
                }
            }
        }
        __syncthreads();    // readers done before next gather overwrites
    }

    // epilogue: point branch + writeout, both nodes
    #pragma unroll
    for (int which = 0; which < 2; which++) {
        const int n = which ? node1 : node0;
        ull* acc = which ? acc1 : acc0;
        const float* zr = z_feats + (size_t)n * FINN;
        float z0 = zr[0], z1 = zr[1], z2 = zr[2];

        float outv[FOUTN];
        #pragma unroll
        for (int i = 0; i < 16; i++) {
            float2 v = unpack2(acc[i]);
            outv[2*i] = v.x; outv[2*i+1] = v.y;
        }
        #pragma unroll
        for (int o = 0; o < FOUTN; o++) {
            float zp = z0 * zw[o] + z1 * zw[FOUTN + o] + z2 * zw[2*FOUTN + o] + zb[o];
            outv[o] += fmaxf(zp, 0.f);
        }
        float4* dst0 = (float4*)(out + (size_t)n * FOUTN);
        #pragma unroll
        for (int j = 0; j < 8; j++)
            dst0[j] = make_float4(outv[4*j], outv[4*j+1], outv[4*j+2], outv[4*j+3]);
        if (copies > 1) {
            float4* dst1 = (float4*)(out + (size_t)N * FOUTN + (size_t)n * FOUTN);
            #pragma unroll
            for (int j = 0; j < 8; j++)
                dst1[j] = make_float4(outv[4*j], outv[4*j+1], outv[4*j+2], outv[4*j+3]);
        }
    }
}

extern "C" void kernel_launch(void* const* d_in, const int* in_sizes, int n_in,
                              void* d_out, int out_size) {
    const float* x_feats   = (const float*)d_in[0];
    const float* z_feats   = (const float*)d_in[1];
    const int*   nbr       = (const int*)d_in[2];
    const float* w1        = (const float*)d_in[3];
    const float* bn1_gamma = (const float*)d_in[4];
    const float* bn1_beta  = (const float*)d_in[5];
    const float* bn1_mean  = (const float*)d_in[6];
    const float* bn1_var   = (const float*)d_in[7];
    const float* w2        = (const float*)d_in[8];
    const float* mlp_w     = (const float*)d_in[9];
    const float* mlp_b     = (const float*)d_in[10];
    const float* mlp_gamma = (const float*)d_in[11];
    const float* mlp_beta  = (const float*)d_in[12];
    const float* mlp_mean  = (const float*)d_in[13];
    const float* mlp_var   = (const float*)d_in[14];

    const int N = in_sizes[0] / FINN;
    const int copies = out_size / (N * FOUTN);

    static int cfg_done = 0;
    if (!cfg_done) {
        (void)cudaFuncSetAttribute(stage2_kernel,
                                   cudaFuncAttributeMaxDynamicSharedMemorySize,
                                   SMEM2_BYTES);
        cfg_done = 1;
    }

    stage1_kernel<<<N / 256, 256>>>(x_feats, nbr, w1,
                                    bn1_gamma, bn1_beta, bn1_mean, bn1_var);
    stage2_kernel<<<N / TILE2, THR2, SMEM2_BYTES>>>(z_feats, nbr, w2,
                                                    mlp_w, mlp_b, mlp_gamma, mlp_beta,
                                                    mlp_mean, mlp_var,
                                                    (float*)d_out, N, copies);
}

// round 11
// speedup vs baseline: 1.8279x; 1.8279x over previous
#include <cuda_runtime.h>
#include <cstdint>

#define NN    131072
#define KK    27
#define FINN  3
#define FOUTN 32
#define EPSB  1e-5f

// Scratch: h [N,32] fp32 (16MB); x padded to 16B rows (2MB)
__device__ __align__(256) float g_h[NN * FOUTN];
__device__ __align__(256) float g_x4[NN * 4];

typedef unsigned long long ull;

__device__ __forceinline__ ull fma2(ull a, ull b, ull c) {
    ull d;
    asm("fma.rn.f32x2 %0, %1, %2, %3;" : "=l"(d) : "l"(a), "l"(b), "l"(c));
    return d;
}
__device__ __forceinline__ ull pack2(float x) {
    ull r; unsigned u = __float_as_uint(x);
    asm("mov.b64 %0, {%1, %2};" : "=l"(r) : "r"(u), "r"(u));
    return r;
}
__device__ __forceinline__ float2 unpack2(ull v) {
    unsigned lo, hi;
    asm("mov.b64 {%0, %1}, %2;" : "=r"(lo), "=r"(hi) : "l"(v));
    return make_float2(__uint_as_float(lo), __uint_as_float(hi));
}
__device__ __forceinline__ unsigned tf32_rn(float v) {
    unsigned r;
    asm("cvt.rna.tf32.f32 %0, %1;" : "=r"(r) : "f"(v));
    return r;
}
// split fp32 -> (tf32 hi, tf32 lo)
__device__ __forceinline__ void split32(float v, unsigned& hi, unsigned& lo) {
    hi = tf32_rn(v);
    lo = tf32_rn(v - __uint_as_float(hi));
}
__device__ __forceinline__ void mma_tf32(float* d,
    unsigned a0, unsigned a1, unsigned a2, unsigned a3,
    unsigned b0, unsigned b1) {
    asm volatile(
        "mma.sync.aligned.m16n8k8.row.col.f32.tf32.tf32.f32 "
        "{%0,%1,%2,%3}, {%4,%5,%6,%7}, {%8,%9}, {%0,%1,%2,%3};"
        : "+f"(d[0]), "+f"(d[1]), "+f"(d[2]), "+f"(d[3])
        : "r"(a0), "r"(a1), "r"(a2), "r"(a3), "r"(b0), "r"(b1));
}

// ============================================================================
// Repack x_feats [N,3] -> g_x4 [N,4]
// ============================================================================
__global__ __launch_bounds__(256)
void repack_kernel(const float* __restrict__ x_feats) {
    const int n = blockIdx.x * blockDim.x + threadIdx.x;
    const float* s = x_feats + (size_t)n * 3;
    ((float4*)g_x4)[n] = make_float4(s[0], s[1], s[2], 0.f);
}

// ============================================================================
// Stage 1 (SIMT, proven): h = silu(bn1(gather(x4) @ w1))
// ============================================================================
__global__ __launch_bounds__(256)
void stage1_kernel(const int*   __restrict__ nbr,
                   const float* __restrict__ w1,
                   const float* __restrict__ gamma1,
                   const float* __restrict__ beta1,
                   const float* __restrict__ mean1,
                   const float* __restrict__ var1)
{
    __shared__ __align__(16) float w1s[KK * FINN * FOUTN];
    __shared__ float s_scale[FOUTN], s_shift[FOUTN];

    const int tid = threadIdx.x;
    for (int i = tid; i < (KK * FINN * FOUTN) / 4; i += blockDim.x)
        ((float4*)w1s)[i] = ((const float4*)w1)[i];
    if (tid < FOUTN) {
        float sc = gamma1[tid] * rsqrtf(var1[tid] + EPSB);
        s_scale[tid] = sc;
        s_shift[tid] = beta1[tid] - mean1[tid] * sc;
    }
    __syncthreads();

    const int n = blockIdx.x * blockDim.x + tid;
    const int* nrow = nbr + (size_t)n * KK;

    ull acc[16];
    #pragma unroll
    for (int i = 0; i < 16; i++) acc[i] = 0ULL;

    int idx_next = nrow[0];
    #pragma unroll 1
    for (int k = 0; k < KK; k++) {
        const int idx = idx_next;
        if (k + 1 < KK) idx_next = nrow[k + 1];
        float4 xv4 = ((const float4*)g_x4)[idx];
        float xv[3] = {xv4.x, xv4.y, xv4.z};
        #pragma unroll
        for (int f = 0; f < FINN; f++) {
            ull s2 = pack2(xv[f]);
            const ulonglong2* wp = (const ulonglong2*)(w1s + (k * FINN + f) * FOUTN);
            #pragma unroll
            for (int j = 0; j < 8; j++) {
                ulonglong2 w = wp[j];
                acc[2 * j]     = fma2(s2, w.x, acc[2 * j]);
                acc[2 * j + 1] = fma2(s2, w.y, acc[2 * j + 1]);
            }
        }
    }

    float outv[FOUTN];
    #pragma unroll
    for (int i = 0; i < 16; i++) {
        float2 v = unpack2(acc[i]);
        outv[2 * i] = v.x; outv[2 * i + 1] = v.y;
    }
    float4* dst = (float4*)(g_h + (size_t)n * FOUTN);
    #pragma unroll
    for (int j = 0; j < 8; j++) {
        float4 o4; float v;
        v = outv[4*j+0] * s_scale[4*j+0] + s_shift[4*j+0]; o4.x = v / (1.f + __expf(-v));
        v = outv[4*j+1] * s_scale[4*j+1] + s_shift[4*j+1]; o4.y = v / (1.f + __expf(-v));
        v = outv[4*j+2] * s_scale[4*j+2] + s_shift[4*j+2]; o4.z = v / (1.f + __expf(-v));
        v = outv[4*j+3] * s_scale[4*j+3] + s_shift[4*j+3]; o4.w = v / (1.f + __expf(-v));
        dst[j] = o4;
    }
}

// ============================================================================
// Stage 2 (mma.sync 3xTF32): D[128,32] = sum_k Hgather_k[128,32] @ w2[k]
// 256 thr = 8 warps x M16; per-k double-buffered gather; B frags via LDG.
// ============================================================================
#define S2T   256
#define TILE  128
#define RST   36                    // stage row stride (floats)
// smem float offsets
#define OFF_B0  0
#define OFF_B1  4608                // 128*36
#define OFF_IDX 9216                // 3456 ints
#define OFF_ZW  12672               // 96
#define OFF_ZB  12768               // 32
#define S2FLOATS 12800
#define S2BYTES  (S2FLOATS * 4)     // 51200

__global__ __launch_bounds__(S2T, 2)
void stage2_mma(const float* __restrict__ z_feats,
                const int*   __restrict__ nbr,
                const float* __restrict__ w2,
                const float* __restrict__ mlp_w,
                const float* __restrict__ mlp_b,
                const float* __restrict__ mlp_gamma,
                const float* __restrict__ mlp_beta,
                const float* __restrict__ mlp_mean,
                const float* __restrict__ mlp_var,
                float* __restrict__ out,
                int N, int copies)
{
    extern __shared__ __align__(16) float sm[];
    float* bufA = sm + OFF_B0;
    float* bufB = sm + OFF_B1;
    int*   idxa = (int*)(sm + OFF_IDX);
    float* zw   = sm + OFF_ZW;
    float* zb   = sm + OFF_ZB;

    const int t = threadIdx.x;
    const int base = blockIdx.x * TILE;

    // ---- prologue: all 128x27 indices -> smem (coalesced int4)
    {
        const int4* nb4 = (const int4*)(nbr + (size_t)base * KK);
        #pragma unroll
        for (int i = 0; i < 4; i++) {
            int e = t + i * 256;
            if (e < (TILE * KK) / 4) ((int4*)idxa)[e] = nb4[e];
        }
    }
    if (t < FOUTN) {
        float sc = mlp_gamma[t] * rsqrtf(mlp_var[t] + EPSB);
        float sh = mlp_beta[t] - mlp_mean[t] * sc;
        zb[t] = mlp_b[t] * sc + sh;
        #pragma unroll
        for (int f = 0; f < FINN; f++)
            zw[f * FOUTN + t] = mlp_w[f * FOUTN + t] * sc;
    }
    __syncthreads();

    // ---- gather k=0 into bufA
    #pragma unroll
    for (int p = 0; p < 4; p++) {
        int s = p * 256 + t, r = s >> 3, gs = s & 7;
        int idx = idxa[r * KK];
        float4 v = ((const float4*)(g_h + (size_t)idx * FOUTN))[gs];
        *(float4*)(bufA + r * RST + gs * 4) = v;
    }
    __syncthreads();

    const int w    = t >> 5;
    const int lane = t & 31;
    const int g    = lane >> 2;     // groupID (0..7)
    const int tig  = lane & 3;      // thread-in-group
    const int row0 = w * 16 + g;

    float d[4][4];
    #pragma unroll
    for (int j = 0; j < 4; j++)
        #pragma unroll
        for (int i = 0; i < 4; i++) d[j][i] = 0.f;

    #pragma unroll 1
    for (int k = 0; k < KK; k++) {
        const float* cb = (k & 1) ? bufB : bufA;
        float* nb = (k & 1) ? bufA : bufB;

        // prefetch gather for k+1 (latency hidden under compute)
        float4 pf[4];
        if (k + 1 < KK) {
            #pragma unroll
            for (int p = 0; p < 4; p++) {
                int s = p * 256 + t, r = s >> 3, gs = s & 7;
                int idx = idxa[r * KK + k + 1];
                pf[p] = ((const float4*)(g_h + (size_t)idx * FOUTN))[gs];
            }
        }

        // compute k
        const float* wk = w2 + (size_t)k * 1024;
        #pragma unroll
        for (int fc = 0; fc < 4; fc++) {
            const int cbase = fc * 8 + tig;
            float a0f = cb[row0 * RST + cbase];
            float a1f = cb[(row0 + 8) * RST + cbase];
            float a2f = cb[row0 * RST + cbase + 4];
            float a3f = cb[(row0 + 8) * RST + cbase + 4];
            unsigned ah0, al0, ah1, al1, ah2, al2, ah3, al3;
            split32(a0f, ah0, al0); split32(a1f, ah1, al1);
            split32(a2f, ah2, al2); split32(a3f, ah3, al3);

            const float* w0 = wk + cbase * FOUTN;        // f = fc*8+tig
            const float* w1p = wk + (cbase + 4) * FOUTN; // f+4
            #pragma unroll
            for (int j = 0; j < 4; j++) {
                float b0f = __ldg(w0 + 8 * j + g);
                float b1f = __ldg(w1p + 8 * j + g);
                unsigned b0h, b0l, b1h, b1l;
                split32(b0f, b0h, b0l);
                split32(b1f, b1h, b1l);
                mma_tf32(d[j], ah0, ah1, ah2, ah3, b0h, b1h);
                mma_tf32(d[j], ah0, ah1, ah2, ah3, b0l, b1l);
                mma_tf32(d[j], al0, al1, al2, al3, b0h, b1h);
            }
        }

        // store prefetched rows into the other buffer
        if (k + 1 < KK) {
            #pragma unroll
            for (int p = 0; p < 4; p++) {
                int s = p * 256 + t, r = s >> 3, gs = s & 7;
                *(float4*)(nb + r * RST + gs * 4) = pf[p];
            }
        }
        __syncthreads();
    }

    // ---- epilogue: D rows row0, row0+8; cols {8j+2tig, 8j+2tig+1}
    const int n0 = base + row0;
    const int n1 = n0 + 8;
    const float* zr0 = z_feats + (size_t)n0 * FINN;
    const float* zr1 = z_feats + (size_t)n1 * FINN;
    float z00 = zr0[0], z01 = zr0[1], z02 = zr0[2];
    float z10 = zr1[0], z11 = zr1[1], z12 = zr1[2];

    #pragma unroll
    for (int j = 0; j < 4; j++) {
        int c = 8 * j + 2 * tig;
        float zw0c = zw[c],     zw1c = zw[FOUTN + c],     zw2c = zw[2*FOUTN + c],     zbc = zb[c];
        float zw0d = zw[c + 1], zw1d = zw[FOUTN + c + 1], zw2d = zw[2*FOUTN + c + 1], zbd = zb[c + 1];

        float2 o0, o1;
        o0.x = d[j][0] + fmaxf(z00 * zw0c + z01 * zw1c + z02 * zw2c + zbc, 0.f);
        o0.y = d[j][1] + fmaxf(z00 * zw0d + z01 * zw1d + z02 * zw2d + zbd, 0.f);
        o1.x = d[j][2] + fmaxf(z10 * zw0c + z11 * zw1c + z12 * zw2c + zbc, 0.f);
        o1.y = d[j][3] + fmaxf(z10 * zw0d + z11 * zw1d + z12 * zw2d + zbd, 0.f);

        *(float2*)(out + (size_t)n0 * FOUTN + c) = o0;
        *(float2*)(out + (size_t)n1 * FOUTN + c) = o1;
        if (copies > 1) {
            *(float2*)(out + (size_t)N * FOUTN + (size_t)n0 * FOUTN + c) = o0;
            *(float2*)(out + (size_t)N * FOUTN + (size_t)n1 * FOUTN + c) = o1;
        }
    }
}

extern "C" void kernel_launch(void* const* d_in, const int* in_sizes, int n_in,
                              void* d_out, int out_size) {
    const float* x_feats   = (const float*)d_in[0];
    const float* z_feats   = (const float*)d_in[1];
    const int*   nbr       = (const int*)d_in[2];
    const float* w1        = (const float*)d_in[3];
    const float* bn1_gamma = (const float*)d_in[4];
    const float* bn1_beta  = (const float*)d_in[5];
    const float* bn1_mean  = (const float*)d_in[6];
    const float* bn1_var   = (const float*)d_in[7];
    const float* w2        = (const float*)d_in[8];
    const float* mlp_w     = (const float*)d_in[9];
    const float* mlp_b     = (const float*)d_in[10];
    const float* mlp_gamma = (const float*)d_in[11];
    const float* mlp_beta  = (const float*)d_in[12];
    const float* mlp_mean  = (const float*)d_in[13];
    const float* mlp_var   = (const float*)d_in[14];

    const int N = in_sizes[0] / FINN;
    const int copies = out_size / (N * FOUTN);

    static int cfg_done = 0;
    if (!cfg_done) {
        (void)cudaFuncSetAttribute(stage2_mma,
                                   cudaFuncAttributeMaxDynamicSharedMemorySize,
                                   S2BYTES);
        cfg_done = 1;
    }

    repack_kernel<<<N / 256, 256>>>(x_feats);
    stage1_kernel<<<N / 256, 256>>>(nbr, w1, bn1_gamma, bn1_beta, bn1_mean, bn1_var);
    stage2_mma<<<N / TILE, S2T, S2BYTES>>>(z_feats, nbr, w2,
                                           mlp_w, mlp_b, mlp_gamma, mlp_beta,
                                           mlp_mean, mlp_var,
                                           (float*)d_out, N, copies);
}